// round 9
// baseline (speedup 1.0000x reference)
#include <cuda_runtime.h>
#include <cuda_bf16.h>
#include <math.h>

// B=8, C=64, H=64, W=64, R=16, HD=4, D=16, K=4, OC=1024
// NPX=32768; x[B,C,H,W]: ch stride 4096, img stride 262144.
#define NPX 32768
#define LSTR 33024   // per-rim list stride

__device__ float    g_cn[64];
__device__ unsigned g_sel[NPX];
__device__ float    g_qkA[1024];
// compaction outputs (kB path)
__device__ int      g_npad;
__device__ int      g_nreal;
__device__ int      g_src[1152];
__device__ int      g_grp[1152];
__device__ float    g_bkq[1152];
__device__ float    g_scl[1152];
__device__ float    g_Wkc[64 * 1024];
// transposed weights
__device__ float    g_WvT[16 * 4096];   // [rim][c][colperm(o)]
__device__ float    g_WmT[16 * 4096];   // [rim][c][colperm(o)]
__device__ float    g_WoT[4096];        // [c][o]
// selection lists / tasks / partial merge results
__device__ unsigned g_cnt[16];
__device__ unsigned g_list[16 * LSTR];          // entry = px | (j<<16)
__device__ unsigned g_tasks[1056];
__device__ int      g_ntask;
__device__ float    g_mpart[NPX * 4 * 64];      // [px][j][c'] written exactly once

__device__ __forceinline__ unsigned long long pk2(float lo, float hi) {
    unsigned long long r;
    asm("mov.b64 %0, {%1, %2};" : "=l"(r) : "f"(lo), "f"(hi));
    return r;
}
__device__ __forceinline__ void fma2(unsigned long long& d, unsigned long long a,
                                     unsigned long long b) {
    asm("fma.rn.f32x2 %0, %1, %2, %0;" : "+l"(d) : "l"(a), "l"(b));
}
__device__ __forceinline__ void unpk(unsigned long long v, float& lo, float& hi) {
    asm("mov.b64 {%0, %1}, %2;" : "=f"(lo), "=f"(hi) : "l"(v));
}

// ============================================================
// Kernel A1a: qk per output channel. 8 blocks x 128.
// ============================================================
__global__ void kA1a(const float* __restrict__ rims, const float* __restrict__ Wq,
                     const float* __restrict__ bq) {
    int o = blockIdx.x * 128 + threadIdx.x;
    int r = o >> 6;
    const float4* rrow = (const float4*)(rims + r * 64);
    const float4* wrow = (const float4*)(Wq + o * 64);
    float s = bq[o];
#pragma unroll
    for (int c4 = 0; c4 < 16; ++c4) {
        float4 w = wrow[c4];
        float4 rv = rrow[c4];
        s = fmaf(rv.x, w.x, s);
        s = fmaf(rv.y, w.y, s);
        s = fmaf(rv.z, w.z, s);
        s = fmaf(rv.w, w.w, s);
    }
    g_qkA[o] = fmaxf(s, 0.f);
}

// ============================================================
// Kernel A1b: null constants + compaction scan + counter zero. 1 x 1024.
// ============================================================
__global__ void kA1b(const float* __restrict__ bk) {
    __shared__ float qs[1024];
    __shared__ int sc[1024];
    int o = threadIdx.x;
    if (o < 16) g_cnt[o] = 0u;
    float qk = g_qkA[o];
    float bko = bk[o];
    qs[o] = qk * fmaxf(bko, 0.f);
    int active = (qk > 0.f) ? 1 : 0;
    sc[o] = active;
    __syncthreads();
    if (o < 64) {
        float cn = 0.f;
#pragma unroll
        for (int d = 0; d < 16; ++d) cn += qs[o * 16 + d];
        g_cn[o] = cn;
    }
    for (int off = 1; off < 1024; off <<= 1) {
        int v = 0;
        if (o >= off) v = sc[o - off];
        __syncthreads();
        sc[o] += v;
        __syncthreads();
    }
    if (active) {
        int p = sc[o] - 1;
        g_src[p] = o;
        g_grp[p] = o >> 4;
        g_bkq[p] = bko * qk;
        g_scl[p] = qk;
    }
    int nact = sc[1023];
    int npad = (nact + 127) & ~127;
    if (o == 0) { g_npad = npad; g_nreal = nact; }
    if (o < npad - nact) {
        int p = nact + o;
        g_src[p] = 0;
        g_grp[p] = 64;
        g_bkq[p] = 0.f;
        g_scl[p] = 0.f;
    }
}

// ============================================================
// Kernel A2: transposed scaled compacted Wk -> g_Wkc[c][slot]. 8 x 256.
// ============================================================
__global__ void kA2(const float* __restrict__ Wk) {
    int row = blockIdx.x * 128 + (threadIdx.x & 127);
    int ch  = (threadIdx.x >> 7) * 32;
    int npad = g_npad;
    if (row >= npad) return;
    float scl = g_scl[row];
    int src = g_src[row];
    const float4* wr = (const float4*)(Wk + src * 64 + ch);
#pragma unroll
    for (int c4 = 0; c4 < 8; ++c4) {
        float4 w = __ldg(wr + c4);
        int c = ch + c4 * 4;
        g_Wkc[(c + 0) * 1024 + row] = w.x * scl;
        g_Wkc[(c + 1) * 1024 + row] = w.y * scl;
        g_Wkc[(c + 2) * 1024 + row] = w.z * scl;
        g_Wkc[(c + 3) * 1024 + row] = w.w * scl;
    }
}

// ============================================================
// Kernel W: one-time weight transposes. 33 blocks x 256.
// Wv/Wm: [rim][o][c] -> [rim][c][colperm(o)], colperm(o) = (o&15)*4 + (o>>4).
// ============================================================
__global__ void kW(const float* __restrict__ Wv, const float* __restrict__ Wm,
                   const float* __restrict__ Wo) {
    int mat = blockIdx.x;
    const float* src;
    float* dst;
    bool perm = true;
    if (mat < 16)      { src = Wv + mat * 4096;       dst = g_WvT + mat * 4096; }
    else if (mat < 32) { src = Wm + (mat - 16) * 4096; dst = g_WmT + (mat - 16) * 4096; }
    else               { src = Wo;                     dst = g_WoT; perm = false; }
    for (int e = threadIdx.x; e < 1024; e += 256) {
        int o = e >> 4, c4 = e & 15;
        float4 v = __ldg((const float4*)src + e);
        int col = perm ? ((o & 15) * 4 + (o >> 4)) : o;
        int c = c4 * 4;
        dst[(c + 0) * 64 + col] = v.x;
        dst[(c + 1) * 64 + col] = v.y;
        dst[(c + 2) * 64 + col] = v.z;
        dst[(c + 3) * 64 + col] = v.w;
    }
}

// ============================================================
// Kernel B: compacted keyf GEMM + scores + top-4. (unchanged)
// ============================================================
#define KB_WS   4096
#define KB_IP   (4096 + 64 * 132)
#define SMEM_B  ((4096 + 64 * 132 + 65 * 68) * 4)

__global__ void __launch_bounds__(256, 2) kB(const float* __restrict__ x) {
    extern __shared__ float sm[];
    float* xs = sm;
    float* ws = sm + KB_WS;
    float* ip = sm + KB_IP;

    const int tid  = threadIdx.x;
    const int pi0  = blockIdx.x * 64;
    const int bimg = pi0 >> 12;
    const int hw   = pi0 & 4095;
    const float* xbase = x + bimg * 262144 + hw;

    for (int e4 = tid; e4 < 1024; e4 += 256) {
        int c = e4 >> 4, p = (e4 & 15) << 2;
        *(float4*)(xs + c * 64 + p) = *(const float4*)(xbase + c * 4096 + p);
    }
    for (int e = tid; e < 65 * 68; e += 256) ip[e] = 0.f;

    const int tx = tid & 15;
    const int ty = tid >> 4;
    const int npad = g_npad;

    for (int o0 = 0; o0 < npad; o0 += 128) {
        __syncthreads();
        for (int e4 = tid; e4 < 2048; e4 += 256) {
            int c = e4 >> 5, o4 = (e4 & 31) << 2;
            *(float4*)(ws + c * 132 + o4) = *(const float4*)(g_Wkc + c * 1024 + o0 + o4);
        }
        __syncthreads();

        unsigned long long acc[16];
#pragma unroll
        for (int i = 0; i < 16; ++i) acc[i] = 0ull;
        const float* wbase = ws + ty * 8;
        const float* xrow  = xs + tx * 4;

#pragma unroll 8
        for (int k = 0; k < 64; ++k) {
            float4 xv = *(const float4*)(xrow + k * 64);
            unsigned long long xd0 = pk2(xv.x, xv.x);
            unsigned long long xd1 = pk2(xv.y, xv.y);
            unsigned long long xd2 = pk2(xv.z, xv.z);
            unsigned long long xd3 = pk2(xv.w, xv.w);
            ulonglong2 wa = *(const ulonglong2*)(wbase + k * 132);
            ulonglong2 wb = *(const ulonglong2*)(wbase + k * 132 + 4);
            fma2(acc[0],  wa.x, xd0); fma2(acc[1],  wa.x, xd1);
            fma2(acc[2],  wa.x, xd2); fma2(acc[3],  wa.x, xd3);
            fma2(acc[4],  wa.y, xd0); fma2(acc[5],  wa.y, xd1);
            fma2(acc[6],  wa.y, xd2); fma2(acc[7],  wa.y, xd3);
            fma2(acc[8],  wb.x, xd0); fma2(acc[9],  wb.x, xd1);
            fma2(acc[10], wb.x, xd2); fma2(acc[11], wb.x, xd3);
            fma2(acc[12], wb.y, xd0); fma2(acc[13], wb.y, xd1);
            fma2(acc[14], wb.y, xd2); fma2(acc[15], wb.y, xd3);
        }

        const int ob = o0 + ty * 8;
        int   grp[8];
        float bkq[8];
#pragma unroll
        for (int j = 0; j < 8; ++j) {
            grp[j] = __ldg(g_grp + ob + j);
            bkq[j] = __ldg(g_bkq + ob + j);
        }
#pragma unroll
        for (int px = 0; px < 4; ++px) {
            float s = 0.f;
            int gp = grp[0];
#pragma unroll
            for (int op = 0; op < 4; ++op) {
                float lo, hi;
                unpk(acc[op * 4 + px], lo, hi);
                int j0 = 2 * op;
                if (grp[j0] != gp) { atomicAdd(ip + gp * 68 + tx * 4 + px, s); s = 0.f; gp = grp[j0]; }
                s += fmaxf(lo + bkq[j0], 0.f);
                if (grp[j0 + 1] != gp) { atomicAdd(ip + gp * 68 + tx * 4 + px, s); s = 0.f; gp = grp[j0 + 1]; }
                s += fmaxf(hi + bkq[j0 + 1], 0.f);
            }
            atomicAdd(ip + gp * 68 + tx * 4 + px, s);
        }
    }
    __syncthreads();

    if (tid < 64) {
        int p = tid;
        float sc[16];
#pragma unroll
        for (int r = 0; r < 16; ++r) {
            float s = 0.f;
#pragma unroll
            for (int hd = 0; hd < 4; ++hd) {
                float v = ip[(r * 4 + hd) * 68 + p] - g_cn[r * 4 + hd];
                s += 1.f / (1.f + expf(-v));
            }
            sc[r] = s;
        }
        unsigned sel = 0;
#pragma unroll
        for (int kk = 0; kk < 4; ++kk) {
            int best = 0;
            float bvv = sc[0];
#pragma unroll
            for (int r = 1; r < 16; ++r)
                if (sc[r] > bvv) { bvv = sc[r]; best = r; }
            sel |= (unsigned)best << (8 * kk);
            sc[best] = -1e30f;
        }
        g_sel[pi0 + p] = sel;
    }
}

// ============================================================
// Kernel Sel: build per-rim global pixel lists. 128 x 256.
// Warp-aggregated atomics on 16 counters.
// ============================================================
__global__ void kSel() {
    int px = blockIdx.x * 256 + threadIdx.x;
    unsigned sel = g_sel[px];
    int lane = threadIdx.x & 31;
#pragma unroll
    for (int j = 0; j < 4; ++j) {
        int r = (sel >> (8 * j)) & 15;
        unsigned mask = __match_any_sync(0xffffffffu, r);
        int leader = __ffs(mask) - 1;
        unsigned base = 0;
        if (lane == leader) base = atomicAdd(&g_cnt[r], __popc(mask));
        base = __shfl_sync(0xffffffffu, base, leader);
        int rank = __popc(mask & ((1u << lane) - 1));
        g_list[r * LSTR + base + rank] = (unsigned)px | ((unsigned)j << 16);
    }
}

// ============================================================
// Kernel Task: tile rim lists into 128-slot tasks. 1 x 32.
// ============================================================
__global__ void kTask() {
    if (threadIdx.x == 0) {
        int n = 0;
        for (int r = 0; r < 16; ++r) {
            int c = (int)g_cnt[r];
            for (int s = 0; s < c; s += 128) g_tasks[n++] = ((unsigned)r << 20) | (unsigned)s;
        }
        g_ntask = n;
    }
}

// ============================================================
// Kernel Cv: one task = (rim, 128 slots). Stage Wv_r/Wm_r in smem,
// gather x columns, val GEMM -> vb, merge GEMM -> g_mpart[(px,j)][c'].
// smem: xg[64][132] + vb[64][132] + ws[64][140] + sp[128] = 104KB -> 2 blk/SM.
// ============================================================
#define CV_VB   8448
#define CV_WS   16896
#define CV_SP   25856
#define SMEM_CV ((25856 + 128) * 4)

__global__ void __launch_bounds__(256, 2) kCv(const float* __restrict__ x,
                                              const float* __restrict__ bv,
                                              const float* __restrict__ bm) {
    if ((int)blockIdx.x >= g_ntask) return;
    extern __shared__ float sm[];
    float* xg = sm;
    float* vb = sm + CV_VB;
    float* ws = sm + CV_WS;
    unsigned* sp = (unsigned*)(sm + CV_SP);

    const int tid = threadIdx.x;
    unsigned tk = g_tasks[blockIdx.x];
    const int r  = tk >> 20;
    const int s0v = tk & 0xFFFFF;
    int n = (int)g_cnt[r] - s0v;
    if (n > 128) n = 128;

    if (tid < 128)
        sp[tid] = (tid < n) ? g_list[r * LSTR + s0v + tid] : 0xFFFFFFFFu;

    // stage Wv_r (cols 0..63) and Wm_r (cols 68..131), stride 140
    for (int e = tid; e < 2048; e += 256) {
        int mat = e >> 10, c = (e >> 4) & 63, o4 = e & 15;
        const float* srcb = (mat ? g_WmT : g_WvT) + r * 4096 + c * 64 + o4 * 4;
        *(float4*)(ws + c * 140 + mat * 68 + o4 * 4) = *(const float4*)srcb;
    }
    __syncthreads();

    // gather xg[c][sl]
    for (int e = tid; e < 8192; e += 256) {
        int c = e >> 7, sl = e & 127;
        unsigned pe = sp[sl];
        float v = 0.f;
        if (pe != 0xFFFFFFFFu) {
            int px = pe & 0x7FFF;
            v = __ldg(x + (px >> 12) * 262144 + c * 4096 + (px & 4095));
        }
        xg[c * 132 + sl] = v;
    }
    __syncthreads();

    // ---- val GEMM: 512 tiles (32 slot-quads x 16 out-quads) ----
    for (int t = tid; t < 512; t += 256) {
        int sq = t >> 4, oq = t & 15, s0 = sq * 4;
        const float* wcol = ws + oq * 4;
        unsigned long long acc[8];
#pragma unroll
        for (int i = 0; i < 8; ++i) acc[i] = 0ull;
#pragma unroll 4
        for (int c = 0; c < 64; ++c) {
            float4 xv = *(const float4*)(xg + c * 132 + s0);
            ulonglong2 wp = *(const ulonglong2*)(wcol + c * 140);
            unsigned long long x0 = pk2(xv.x, xv.x);
            unsigned long long x1 = pk2(xv.y, xv.y);
            unsigned long long x2 = pk2(xv.z, xv.z);
            unsigned long long x3 = pk2(xv.w, xv.w);
            fma2(acc[0], wp.x, x0); fma2(acc[1], wp.x, x1);
            fma2(acc[2], wp.x, x2); fma2(acc[3], wp.x, x3);
            fma2(acc[4], wp.y, x0); fma2(acc[5], wp.y, x1);
            fma2(acc[6], wp.y, x2); fma2(acc[7], wp.y, x3);
        }
        float b0 = __ldg(bv + r * 64 + oq);
        float b1 = __ldg(bv + r * 64 + oq + 16);
        float b2 = __ldg(bv + r * 64 + oq + 32);
        float b3 = __ldg(bv + r * 64 + oq + 48);
#pragma unroll
        for (int sl = 0; sl < 4; ++sl) {
            float lo, hi;
            unpk(acc[sl], lo, hi);
            vb[(oq)      * 132 + s0 + sl] = fmaxf(lo + b0, 0.f);
            vb[(oq + 16) * 132 + s0 + sl] = fmaxf(hi + b1, 0.f);
            unpk(acc[4 + sl], lo, hi);
            vb[(oq + 32) * 132 + s0 + sl] = fmaxf(lo + b2, 0.f);
            vb[(oq + 48) * 132 + s0 + sl] = fmaxf(hi + b3, 0.f);
        }
    }
    __syncthreads();

    // ---- merge GEMM + scatter to g_mpart ----
    for (int t = tid; t < 512; t += 256) {
        int sq = t >> 4, oq = t & 15, s0 = sq * 4;
        const float* wcol = ws + 68 + oq * 4;
        unsigned long long acc[8];
#pragma unroll
        for (int i = 0; i < 8; ++i) acc[i] = 0ull;
#pragma unroll 4
        for (int d = 0; d < 64; ++d) {
            float4 xv = *(const float4*)(vb + d * 132 + s0);
            ulonglong2 wp = *(const ulonglong2*)(wcol + d * 140);
            unsigned long long x0 = pk2(xv.x, xv.x);
            unsigned long long x1 = pk2(xv.y, xv.y);
            unsigned long long x2 = pk2(xv.z, xv.z);
            unsigned long long x3 = pk2(xv.w, xv.w);
            fma2(acc[0], wp.x, x0); fma2(acc[1], wp.x, x1);
            fma2(acc[2], wp.x, x2); fma2(acc[3], wp.x, x3);
            fma2(acc[4], wp.y, x0); fma2(acc[5], wp.y, x1);
            fma2(acc[6], wp.y, x2); fma2(acc[7], wp.y, x3);
        }
        float b0 = __ldg(bm + r * 64 + oq);
        float b1 = __ldg(bm + r * 64 + oq + 16);
        float b2 = __ldg(bm + r * 64 + oq + 32);
        float b3 = __ldg(bm + r * 64 + oq + 48);
#pragma unroll
        for (int sl = 0; sl < 4; ++sl) {
            unsigned pe = sp[s0 + sl];
            if (pe == 0xFFFFFFFFu) continue;
            int px = pe & 0x7FFF;
            int j  = (pe >> 16) & 3;
            float* mp = g_mpart + ((px << 2) + j) * 64;
            float lo, hi;
            unpk(acc[sl], lo, hi);
            mp[oq]      = lo + b0;
            mp[oq + 16] = hi + b1;
            unpk(acc[4 + sl], lo, hi);
            mp[oq + 32] = lo + b2;
            mp[oq + 48] = hi + b3;
        }
    }
}

// ============================================================
// Kernel D: reduce 4 parts, mean+relu, out projection. 128 x 256.
// smem: mt[64][260] + wo[64][68] = 84KB -> 2 blk/SM.
// ============================================================
#define KD_WO   16640
#define SMEM_D  ((16640 + 64 * 68) * 4)

__global__ void __launch_bounds__(256, 2) kD(const float* __restrict__ bo,
                                             float* __restrict__ out) {
    extern __shared__ float sm[];
    float* mt = sm;              // [c][px] 64 x 260
    float* wo = sm + KD_WO;      // [c][o]  64 x 68

    const int tid = threadIdx.x;
    const int pi0 = blockIdx.x * 256;

    for (int e4 = tid; e4 < 1024; e4 += 256) {
        int c = e4 >> 4, o4 = (e4 & 15) << 2;
        *(float4*)(wo + c * 68 + o4) = *(const float4*)(g_WoT + c * 64 + o4);
    }

    // load mpart (4 parts), mean+relu, transpose into mt
    for (int e = tid; e < 4096; e += 256) {
        int pxl = e & 255, c4 = e >> 8;
        const float4* mp = (const float4*)(g_mpart + (unsigned)(pi0 + pxl) * 256) + c4;
        float4 a = __ldg(mp);
        float4 b = __ldg(mp + 16);
        float4 c = __ldg(mp + 32);
        float4 d = __ldg(mp + 48);
        float v0 = fmaxf((a.x + b.x + c.x + d.x) * 0.25f, 0.f);
        float v1 = fmaxf((a.y + b.y + c.y + d.y) * 0.25f, 0.f);
        float v2 = fmaxf((a.z + b.z + c.z + d.z) * 0.25f, 0.f);
        float v3 = fmaxf((a.w + b.w + c.w + d.w) * 0.25f, 0.f);
        int cc = c4 * 4;
        mt[(cc + 0) * 260 + pxl] = v0;
        mt[(cc + 1) * 260 + pxl] = v1;
        mt[(cc + 2) * 260 + pxl] = v2;
        mt[(cc + 3) * 260 + pxl] = v3;
    }
    __syncthreads();

    // projection: 1024 tiles = 128 pixel-pairs x 8 out-octets
    for (int t = tid; t < 1024; t += 256) {
        int pq = t & 127, oc = t >> 7;
        unsigned long long acc[8];
#pragma unroll
        for (int j = 0; j < 8; ++j) acc[j] = 0ull;
#pragma unroll 4
        for (int c = 0; c < 64; ++c) {
            unsigned long long mv = *(const unsigned long long*)(mt + c * 260 + pq * 2);
            float4 wA = *(const float4*)(wo + c * 68 + oc * 8);
            float4 wB = *(const float4*)(wo + c * 68 + oc * 8 + 4);
            fma2(acc[0], mv, pk2(wA.x, wA.x));
            fma2(acc[1], mv, pk2(wA.y, wA.y));
            fma2(acc[2], mv, pk2(wA.z, wA.z));
            fma2(acc[3], mv, pk2(wA.w, wA.w));
            fma2(acc[4], mv, pk2(wB.x, wB.x));
            fma2(acc[5], mv, pk2(wB.y, wB.y));
            fma2(acc[6], mv, pk2(wB.z, wB.z));
            fma2(acc[7], mv, pk2(wB.w, wB.w));
        }
        int pxg = pi0 + pq * 2;
        float* outb = out + (pxg >> 12) * 262144 + (pxg & 4095);
#pragma unroll
        for (int j = 0; j < 8; ++j) {
            int co = oc * 8 + j;
            float bov = __ldg(bo + co);
            float lo, hi;
            unpk(acc[j], lo, hi);
            float2 o2 = make_float2(fmaxf(lo + bov, 0.f), fmaxf(hi + bov, 0.f));
            *(float2*)(outb + co * 4096) = o2;
        }
    }
}

// ============================================================
extern "C" void kernel_launch(void* const* d_in, const int* in_sizes, int n_in,
                              void* d_out, int out_size) {
    const float* x    = (const float*)d_in[0];
    const float* rims = (const float*)d_in[1];
    const float* Wk   = (const float*)d_in[2];
    const float* bk   = (const float*)d_in[3];
    const float* Wv   = (const float*)d_in[4];
    const float* bv   = (const float*)d_in[5];
    const float* Wq   = (const float*)d_in[6];
    const float* bq   = (const float*)d_in[7];
    const float* Wm   = (const float*)d_in[8];
    const float* bm   = (const float*)d_in[9];
    const float* Wo   = (const float*)d_in[10];
    const float* bo   = (const float*)d_in[11];
    float* out = (float*)d_out;

    cudaFuncSetAttribute(kB,  cudaFuncAttributeMaxDynamicSharedMemorySize, SMEM_B);
    cudaFuncSetAttribute(kCv, cudaFuncAttributeMaxDynamicSharedMemorySize, SMEM_CV);
    cudaFuncSetAttribute(kD,  cudaFuncAttributeMaxDynamicSharedMemorySize, SMEM_D);

    kA1a<<<8, 128>>>(rims, Wq, bq);
    kW<<<33, 256>>>(Wv, Wm, Wo);
    kA1b<<<1, 1024>>>(bk);
    kA2<<<8, 256>>>(Wk);
    kB<<<512, 256, SMEM_B>>>(x);
    kSel<<<128, 256>>>();
    kTask<<<1, 32>>>();
    kCv<<<1040, 256, SMEM_CV>>>(x, bv, bm);
    kD<<<128, 256, SMEM_D>>>(bo, out);
}

// round 11
// speedup vs baseline: 1.4788x; 1.4788x over previous
#include <cuda_runtime.h>
#include <cuda_bf16.h>
#include <math.h>

// B=8, C=64, H=64, W=64, R=16, HD=4, D=16, K=4, OC=1024
// NPX=32768; x[B,C,H,W]: ch stride 4096, img stride 262144.
#define NPX 32768

__device__ float    g_cn[64];
__device__ unsigned g_sel[NPX];
__device__ float    g_qkA[1024];
// compaction outputs (kB path)
__device__ int      g_npad;
__device__ int      g_nreal;
__device__ int      g_src[1152];
__device__ int      g_grp[1152];
__device__ float    g_bkq[1152];
__device__ float    g_scl[1152];
__device__ float    g_Wkc[64 * 1024];
// transposed weights for kC
__device__ float    g_WvT[16 * 4096];   // [rim][c][colperm(o)]
__device__ float    g_WmT[16 * 4096];   // [rim][c][colperm(o)]
__device__ float    g_WoT[4096];        // [c][o]

__device__ __forceinline__ unsigned long long pk2(float lo, float hi) {
    unsigned long long r;
    asm("mov.b64 %0, {%1, %2};" : "=l"(r) : "f"(lo), "f"(hi));
    return r;
}
__device__ __forceinline__ void fma2(unsigned long long& d, unsigned long long a,
                                     unsigned long long b) {
    asm("fma.rn.f32x2 %0, %1, %2, %0;" : "+l"(d) : "l"(a), "l"(b));
}
__device__ __forceinline__ void unpk(unsigned long long v, float& lo, float& hi) {
    asm("mov.b64 {%0, %1}, %2;" : "=f"(lo), "=f"(hi) : "l"(v));
}

// ============================================================
// Kernel A1a: qk per output channel. 8 blocks x 128.
// ============================================================
__global__ void kA1a(const float* __restrict__ rims, const float* __restrict__ Wq,
                     const float* __restrict__ bq) {
    int o = blockIdx.x * 128 + threadIdx.x;
    int r = o >> 6;
    const float4* rrow = (const float4*)(rims + r * 64);
    const float4* wrow = (const float4*)(Wq + o * 64);
    float s = bq[o];
#pragma unroll
    for (int c4 = 0; c4 < 16; ++c4) {
        float4 w = wrow[c4];
        float4 rv = rrow[c4];
        s = fmaf(rv.x, w.x, s);
        s = fmaf(rv.y, w.y, s);
        s = fmaf(rv.z, w.z, s);
        s = fmaf(rv.w, w.w, s);
    }
    g_qkA[o] = fmaxf(s, 0.f);
}

// ============================================================
// Kernel A1b: null constants + compaction scan. 1 x 1024.
// ============================================================
__global__ void kA1b(const float* __restrict__ bk) {
    __shared__ float qs[1024];
    __shared__ int sc[1024];
    int o = threadIdx.x;
    float qk = g_qkA[o];
    float bko = bk[o];
    qs[o] = qk * fmaxf(bko, 0.f);
    int active = (qk > 0.f) ? 1 : 0;
    sc[o] = active;
    __syncthreads();
    if (o < 64) {
        float cn = 0.f;
#pragma unroll
        for (int d = 0; d < 16; ++d) cn += qs[o * 16 + d];
        g_cn[o] = cn;
    }
    for (int off = 1; off < 1024; off <<= 1) {
        int v = 0;
        if (o >= off) v = sc[o - off];
        __syncthreads();
        sc[o] += v;
        __syncthreads();
    }
    if (active) {
        int p = sc[o] - 1;
        g_src[p] = o;
        g_grp[p] = o >> 4;
        g_bkq[p] = bko * qk;
        g_scl[p] = qk;
    }
    int nact = sc[1023];
    int npad = (nact + 127) & ~127;
    if (o == 0) { g_npad = npad; g_nreal = nact; }
    if (o < npad - nact) {
        int p = nact + o;
        g_src[p] = 0;
        g_grp[p] = 64;
        g_bkq[p] = 0.f;
        g_scl[p] = 0.f;
    }
}

// ============================================================
// Kernel A2: transposed scaled compacted Wk -> g_Wkc[c][slot]. 32 x 256.
// ============================================================
__global__ void kA2(const float* __restrict__ Wk) {
    int gid = blockIdx.x * 256 + threadIdx.x;   // 8192
    int row = gid >> 3, seg = gid & 7;          // 8 channels per seg
    if (row >= g_npad) return;
    float scl = g_scl[row];
    int src = g_src[row];
    const float4* wr = (const float4*)(Wk + src * 64 + seg * 8);
    float4 w0 = __ldg(wr);
    float4 w1 = __ldg(wr + 1);
    int c = seg * 8;
    g_Wkc[(c + 0) * 1024 + row] = w0.x * scl;
    g_Wkc[(c + 1) * 1024 + row] = w0.y * scl;
    g_Wkc[(c + 2) * 1024 + row] = w0.z * scl;
    g_Wkc[(c + 3) * 1024 + row] = w0.w * scl;
    g_Wkc[(c + 4) * 1024 + row] = w1.x * scl;
    g_Wkc[(c + 5) * 1024 + row] = w1.y * scl;
    g_Wkc[(c + 6) * 1024 + row] = w1.z * scl;
    g_Wkc[(c + 7) * 1024 + row] = w1.w * scl;
}

// ============================================================
// Kernel W: one-time weight transposes. 33 blocks x 256.
// Wv/Wm: [rim][o][c] -> [rim][c][colperm(o)], colperm(o) = (o&15)*4 + (o>>4).
// ============================================================
__global__ void kW(const float* __restrict__ Wv, const float* __restrict__ Wm,
                   const float* __restrict__ Wo) {
    int mat = blockIdx.x;
    const float* src;
    float* dst;
    bool perm = true;
    if (mat < 16)      { src = Wv + mat * 4096;       dst = g_WvT + mat * 4096; }
    else if (mat < 32) { src = Wm + (mat - 16) * 4096; dst = g_WmT + (mat - 16) * 4096; }
    else               { src = Wo;                     dst = g_WoT; perm = false; }
    for (int e = threadIdx.x; e < 1024; e += 256) {
        int o = e >> 4, c4 = e & 15;
        float4 v = __ldg((const float4*)src + e);
        int col = perm ? ((o & 15) * 4 + (o >> 4)) : o;
        int c = c4 * 4;
        dst[(c + 0) * 64 + col] = v.x;
        dst[(c + 1) * 64 + col] = v.y;
        dst[(c + 2) * 64 + col] = v.z;
        dst[(c + 3) * 64 + col] = v.w;
    }
}

// ============================================================
// Kernel B: compacted keyf GEMM + scores + top-4. (unchanged)
// ============================================================
#define KB_WS   4096
#define KB_IP   (4096 + 64 * 132)
#define SMEM_B  ((4096 + 64 * 132 + 65 * 68) * 4)

__global__ void __launch_bounds__(256, 2) kB(const float* __restrict__ x) {
    extern __shared__ float sm[];
    float* xs = sm;
    float* ws = sm + KB_WS;
    float* ip = sm + KB_IP;

    const int tid  = threadIdx.x;
    const int pi0  = blockIdx.x * 64;
    const int bimg = pi0 >> 12;
    const int hw   = pi0 & 4095;
    const float* xbase = x + bimg * 262144 + hw;

    for (int e4 = tid; e4 < 1024; e4 += 256) {
        int c = e4 >> 4, p = (e4 & 15) << 2;
        *(float4*)(xs + c * 64 + p) = *(const float4*)(xbase + c * 4096 + p);
    }
    for (int e = tid; e < 65 * 68; e += 256) ip[e] = 0.f;

    const int tx = tid & 15;
    const int ty = tid >> 4;
    const int npad = g_npad;

    for (int o0 = 0; o0 < npad; o0 += 128) {
        __syncthreads();
        for (int e4 = tid; e4 < 2048; e4 += 256) {
            int c = e4 >> 5, o4 = (e4 & 31) << 2;
            *(float4*)(ws + c * 132 + o4) = *(const float4*)(g_Wkc + c * 1024 + o0 + o4);
        }
        __syncthreads();

        unsigned long long acc[16];
#pragma unroll
        for (int i = 0; i < 16; ++i) acc[i] = 0ull;
        const float* wbase = ws + ty * 8;
        const float* xrow  = xs + tx * 4;

#pragma unroll 8
        for (int k = 0; k < 64; ++k) {
            float4 xv = *(const float4*)(xrow + k * 64);
            unsigned long long xd0 = pk2(xv.x, xv.x);
            unsigned long long xd1 = pk2(xv.y, xv.y);
            unsigned long long xd2 = pk2(xv.z, xv.z);
            unsigned long long xd3 = pk2(xv.w, xv.w);
            ulonglong2 wa = *(const ulonglong2*)(wbase + k * 132);
            ulonglong2 wb = *(const ulonglong2*)(wbase + k * 132 + 4);
            fma2(acc[0],  wa.x, xd0); fma2(acc[1],  wa.x, xd1);
            fma2(acc[2],  wa.x, xd2); fma2(acc[3],  wa.x, xd3);
            fma2(acc[4],  wa.y, xd0); fma2(acc[5],  wa.y, xd1);
            fma2(acc[6],  wa.y, xd2); fma2(acc[7],  wa.y, xd3);
            fma2(acc[8],  wb.x, xd0); fma2(acc[9],  wb.x, xd1);
            fma2(acc[10], wb.x, xd2); fma2(acc[11], wb.x, xd3);
            fma2(acc[12], wb.y, xd0); fma2(acc[13], wb.y, xd1);
            fma2(acc[14], wb.y, xd2); fma2(acc[15], wb.y, xd3);
        }

        const int ob = o0 + ty * 8;
        int   grp[8];
        float bkq[8];
#pragma unroll
        for (int j = 0; j < 8; ++j) {
            grp[j] = __ldg(g_grp + ob + j);
            bkq[j] = __ldg(g_bkq + ob + j);
        }
#pragma unroll
        for (int px = 0; px < 4; ++px) {
            float s = 0.f;
            int gp = grp[0];
#pragma unroll
            for (int op = 0; op < 4; ++op) {
                float lo, hi;
                unpk(acc[op * 4 + px], lo, hi);
                int j0 = 2 * op;
                if (grp[j0] != gp) { atomicAdd(ip + gp * 68 + tx * 4 + px, s); s = 0.f; gp = grp[j0]; }
                s += fmaxf(lo + bkq[j0], 0.f);
                if (grp[j0 + 1] != gp) { atomicAdd(ip + gp * 68 + tx * 4 + px, s); s = 0.f; gp = grp[j0 + 1]; }
                s += fmaxf(hi + bkq[j0 + 1], 0.f);
            }
            atomicAdd(ip + gp * 68 + tx * 4 + px, s);
        }
    }
    __syncthreads();

    if (tid < 64) {
        int p = tid;
        float sc[16];
#pragma unroll
        for (int r = 0; r < 16; ++r) {
            float s = 0.f;
#pragma unroll
            for (int hd = 0; hd < 4; ++hd) {
                float v = ip[(r * 4 + hd) * 68 + p] - g_cn[r * 4 + hd];
                s += 1.f / (1.f + expf(-v));
            }
            sc[r] = s;
        }
        unsigned sel = 0;
#pragma unroll
        for (int kk = 0; kk < 4; ++kk) {
            int best = 0;
            float bvv = sc[0];
#pragma unroll
            for (int r = 1; r < 16; ++r)
                if (sc[r] > bvv) { bvv = sc[r]; best = r; }
            sel |= (unsigned)best << (8 * kk);
            sc[best] = -1e30f;
        }
        g_sel[pi0 + p] = sel;
    }
}

// ============================================================
// Kernel C: block = 256 px, 512 threads, grid 128 (one wave, 16 warps/SM).
// Rim batches of 2; ws-staged weights; windows of 128 slots; f32x2 GEMMs;
// gather direct from global (block-local pixels); Wo staged for projection.
// smem floats:
//   macc[64][266]  @0      17024
//   xg  [64][140]  @17024   8960
//   vb  [64][140]  @25984   8960
//   ws  [64][280]  @34944  17920   (val: m*68+col; merge: +140)
//   bias           @52864    256   (bvS[128], bmS[128]; bvS reused for bo)
//   rimcnt/pn      @53120     32
//   rimlist u16[16][256] @53152  2048
// ============================================================
#define C_MACC 0
#define C_XG   17024
#define C_VB   25984
#define C_WS   34944
#define C_BIAS 52864
#define C_CNT  53120
#define C_RL   53152
#define SMEM_C ((53152 + 2048) * 4)

__global__ void __launch_bounds__(512, 1) kC(const float* __restrict__ x,
                                             const float* __restrict__ bv,
                                             const float* __restrict__ bm,
                                             const float* __restrict__ bo,
                                             float* __restrict__ out) {
    extern __shared__ float sm[];
    float* macc = sm + C_MACC;
    float* xg   = sm + C_XG;
    float* vb   = sm + C_VB;
    float* ws   = sm + C_WS;
    float* bvS  = sm + C_BIAS;        // [2][64]
    float* bmS  = bvS + 128;          // [2][64]
    int* rimcnt = (int*)(sm + C_CNT);
    int* pn     = rimcnt + 16;
    unsigned short* rimlist = (unsigned short*)(sm + C_RL);   // [16][256]

    const int tid  = threadIdx.x;
    const int pi0  = blockIdx.x * 256;
    const int bimg = pi0 >> 12;
    const int hwb  = pi0 & 4095;
    const float* xbase = x + bimg * 262144 + hwb;

    for (int e = tid; e < 17024; e += 512) macc[e] = 0.f;
    if (tid < 16) rimcnt[tid] = 0;
    __syncthreads();

    if (tid < 256) {
        unsigned sel = g_sel[pi0 + tid];
#pragma unroll
        for (int j = 0; j < 4; ++j) {
            int r = (sel >> (8 * j)) & 15;
            int slot = atomicAdd(&rimcnt[r], 1);
            rimlist[r * 256 + slot] = (unsigned short)tid;
        }
    }
    __syncthreads();
    if (tid < 16) pn[tid] = (rimcnt[tid] + 3) & ~3;
    __syncthreads();

    const int sq = tid >> 4, oq = tid & 15, s0 = sq * 4;

    for (int b = 0; b < 8; ++b) {
        const int r0 = 2 * b;
        const int pn0 = pn[r0];
        const int nsl = pn0 + pn[r0 + 1];

        // stage Wv/Wm (both rims) + biases
        for (int e = tid; e < 4096; e += 512) {
            int mat = e >> 11;
            int rest = e & 2047;
            int m = rest >> 10, c = (rest >> 4) & 63, o4 = rest & 15;
            const float* srcb = (mat ? g_WmT : g_WvT) + (r0 + m) * 4096 + c * 64 + o4 * 4;
            *(float4*)(ws + c * 280 + mat * 140 + m * 68 + o4 * 4) = *(const float4*)srcb;
        }
        if (tid < 128) {
            int m = tid >> 6, o = tid & 63;
            bvS[tid] = __ldg(bv + (r0 + m) * 64 + o);
            bmS[tid] = __ldg(bm + (r0 + m) * 64 + o);
        }
        __syncthreads();

        for (int w0 = 0; w0 < nsl; w0 += 128) {
            // ---- gather: thread owns slot sl across 16 channels ----
            {
                int sl = tid & 127;
                int gs = w0 + sl;
                int mm = (gs >= pn0) ? 1 : 0;
                int rim = r0 + mm;
                int i = gs - (mm ? pn0 : 0);
                bool ok = (i < rimcnt[rim]);
                int pxl = ok ? (int)rimlist[rim * 256 + i] : 0;
                for (int c = tid >> 7; c < 64; c += 4) {
                    float v = ok ? __ldg(xbase + c * 4096 + pxl) : 0.f;
                    xg[c * 140 + sl] = v;
                }
            }
            __syncthreads();

            const int m2 = ((w0 + s0) >= pn0) ? 1 : 0;

            // ---- val GEMM: 1 tile per thread (4 slots x out-quad oq) ----
            {
                const float* wcol = ws + m2 * 68 + oq * 4;
                unsigned long long acc[8];
#pragma unroll
                for (int i = 0; i < 8; ++i) acc[i] = 0ull;
#pragma unroll 4
                for (int c = 0; c < 64; ++c) {
                    float4 xv = *(const float4*)(xg + c * 140 + s0);
                    ulonglong2 wp = *(const ulonglong2*)(wcol + c * 280);
                    unsigned long long x0 = pk2(xv.x, xv.x);
                    unsigned long long x1 = pk2(xv.y, xv.y);
                    unsigned long long x2 = pk2(xv.z, xv.z);
                    unsigned long long x3 = pk2(xv.w, xv.w);
                    fma2(acc[0], wp.x, x0); fma2(acc[1], wp.x, x1);
                    fma2(acc[2], wp.x, x2); fma2(acc[3], wp.x, x3);
                    fma2(acc[4], wp.y, x0); fma2(acc[5], wp.y, x1);
                    fma2(acc[6], wp.y, x2); fma2(acc[7], wp.y, x3);
                }
                float b0 = bvS[m2 * 64 + oq];
                float b1 = bvS[m2 * 64 + oq + 16];
                float b2 = bvS[m2 * 64 + oq + 32];
                float b3 = bvS[m2 * 64 + oq + 48];
#pragma unroll
                for (int j = 0; j < 4; ++j) {
                    float lo, hi;
                    unpk(acc[j], lo, hi);
                    vb[(oq)      * 140 + s0 + j] = fmaxf(lo + b0, 0.f);
                    vb[(oq + 16) * 140 + s0 + j] = fmaxf(hi + b1, 0.f);
                    unpk(acc[4 + j], lo, hi);
                    vb[(oq + 32) * 140 + s0 + j] = fmaxf(lo + b2, 0.f);
                    vb[(oq + 48) * 140 + s0 + j] = fmaxf(hi + b3, 0.f);
                }
            }
            __syncthreads();

            // ---- merge GEMM + scatter ----
            {
                const float* wcol = ws + 140 + m2 * 68 + oq * 4;
                unsigned long long acc[8];
#pragma unroll
                for (int i = 0; i < 8; ++i) acc[i] = 0ull;
#pragma unroll 4
                for (int d = 0; d < 64; ++d) {
                    float4 xv = *(const float4*)(vb + d * 140 + s0);
                    ulonglong2 wp = *(const ulonglong2*)(wcol + d * 280);
                    unsigned long long x0 = pk2(xv.x, xv.x);
                    unsigned long long x1 = pk2(xv.y, xv.y);
                    unsigned long long x2 = pk2(xv.z, xv.z);
                    unsigned long long x3 = pk2(xv.w, xv.w);
                    fma2(acc[0], wp.x, x0); fma2(acc[1], wp.x, x1);
                    fma2(acc[2], wp.x, x2); fma2(acc[3], wp.x, x3);
                    fma2(acc[4], wp.y, x0); fma2(acc[5], wp.y, x1);
                    fma2(acc[6], wp.y, x2); fma2(acc[7], wp.y, x3);
                }
                float b0 = bmS[m2 * 64 + oq];
                float b1 = bmS[m2 * 64 + oq + 16];
                float b2 = bmS[m2 * 64 + oq + 32];
                float b3 = bmS[m2 * 64 + oq + 48];
                const int rim = r0 + m2;
                const int base = (w0 + s0) - (m2 ? pn0 : 0);
#pragma unroll
                for (int j = 0; j < 4; ++j) {
                    int i = base + j;
                    if (i < rimcnt[rim]) {
                        int pxl = (int)rimlist[rim * 256 + i];
                        float lo, hi;
                        unpk(acc[j], lo, hi);
                        atomicAdd(macc + (oq)      * 266 + pxl, lo + b0);
                        atomicAdd(macc + (oq + 16) * 266 + pxl, hi + b1);
                        unpk(acc[4 + j], lo, hi);
                        atomicAdd(macc + (oq + 32) * 266 + pxl, lo + b2);
                        atomicAdd(macc + (oq + 48) * 266 + pxl, hi + b3);
                    }
                }
            }
            __syncthreads();
        }
    }

    // mean+relu; stage Wo into ws cols 0..63 and bo into bvS
    for (int e = tid; e < 16384; e += 512) {
        int c = e >> 8, p = e & 255;
        macc[c * 266 + p] = fmaxf(macc[c * 266 + p] * 0.25f, 0.f);
    }
    for (int e4 = tid; e4 < 1024; e4 += 512) {
        int c = e4 >> 4, o4 = (e4 & 15) << 2;
        *(float4*)(ws + c * 280 + o4) = *(const float4*)(g_WoT + c * 64 + o4);
    }
    if (tid < 64) bvS[tid] = __ldg(bo + tid);
    __syncthreads();

    // projection: 1024 tiles = 128 pixel-pairs x 8 out-octets, 2 per thread
    for (int t = tid; t < 1024; t += 512) {
        int pq = t & 127, oc = t >> 7;
        unsigned long long acc[8];
#pragma unroll
        for (int j = 0; j < 8; ++j) acc[j] = 0ull;
#pragma unroll 4
        for (int c = 0; c < 64; ++c) {
            unsigned long long mv = *(const unsigned long long*)(macc + c * 266 + pq * 2);
            float4 wA = *(const float4*)(ws + c * 280 + oc * 8);
            float4 wB = *(const float4*)(ws + c * 280 + oc * 8 + 4);
            fma2(acc[0], mv, pk2(wA.x, wA.x));
            fma2(acc[1], mv, pk2(wA.y, wA.y));
            fma2(acc[2], mv, pk2(wA.z, wA.z));
            fma2(acc[3], mv, pk2(wA.w, wA.w));
            fma2(acc[4], mv, pk2(wB.x, wB.x));
            fma2(acc[5], mv, pk2(wB.y, wB.y));
            fma2(acc[6], mv, pk2(wB.z, wB.z));
            fma2(acc[7], mv, pk2(wB.w, wB.w));
        }
        float* outb = out + bimg * 262144 + hwb + pq * 2;
#pragma unroll
        for (int j = 0; j < 8; ++j) {
            int co = oc * 8 + j;
            float bov = bvS[co];
            float lo, hi;
            unpk(acc[j], lo, hi);
            float2 o2 = make_float2(fmaxf(lo + bov, 0.f), fmaxf(hi + bov, 0.f));
            *(float2*)(outb + co * 4096) = o2;
        }
    }
}

// ============================================================
extern "C" void kernel_launch(void* const* d_in, const int* in_sizes, int n_in,
                              void* d_out, int out_size) {
    const float* x    = (const float*)d_in[0];
    const float* rims = (const float*)d_in[1];
    const float* Wk   = (const float*)d_in[2];
    const float* bk   = (const float*)d_in[3];
    const float* Wv   = (const float*)d_in[4];
    const float* bv   = (const float*)d_in[5];
    const float* Wq   = (const float*)d_in[6];
    const float* bq   = (const float*)d_in[7];
    const float* Wm   = (const float*)d_in[8];
    const float* bm   = (const float*)d_in[9];
    const float* Wo   = (const float*)d_in[10];
    const float* bo   = (const float*)d_in[11];
    float* out = (float*)d_out;

    cudaFuncSetAttribute(kB, cudaFuncAttributeMaxDynamicSharedMemorySize, SMEM_B);
    cudaFuncSetAttribute(kC, cudaFuncAttributeMaxDynamicSharedMemorySize, SMEM_C);

    kA1a<<<8, 128>>>(rims, Wq, bq);
    kW<<<33, 256>>>(Wv, Wm, Wo);
    kA1b<<<1, 1024>>>(bk);
    kA2<<<32, 256>>>(Wk);
    kB<<<512, 256, SMEM_B>>>(x);
    kC<<<128, 512, SMEM_C>>>(x, bv, bm, bo, out);
}

// round 14
// speedup vs baseline: 1.6533x; 1.1180x over previous
#include <cuda_runtime.h>
#include <cuda_bf16.h>
#include <math.h>

// B=8, C=64, H=64, W=64, R=16, HD=4, D=16, K=4, OC=1024
// NPX=32768; x[B,C,H,W]: ch stride 4096, img stride 262144.
#define NPX 32768

__device__ float    g_cn[64];
__device__ unsigned g_sel[NPX];
__device__ float    g_qkA[1024];
// compaction outputs (kB path)
__device__ int      g_npad;
__device__ int      g_nreal;
__device__ int      g_src[1152];
__device__ int      g_grp[1152];
__device__ float    g_bkq[1152];
__device__ float    g_scl[1152];
__device__ float    g_Wkc[64 * 1024];
// transposed weights for kC
__device__ float    g_WvT[16 * 4096];   // [rim][c][colperm(o)]
__device__ float    g_WmT[16 * 4096];   // [rim][c][colperm(o)]
__device__ float    g_WoT[4096];        // [c][o]

__device__ __forceinline__ unsigned long long pk2(float lo, float hi) {
    unsigned long long r;
    asm("mov.b64 %0, {%1, %2};" : "=l"(r) : "f"(lo), "f"(hi));
    return r;
}
__device__ __forceinline__ void fma2(unsigned long long& d, unsigned long long a,
                                     unsigned long long b) {
    asm("fma.rn.f32x2 %0, %1, %2, %0;" : "+l"(d) : "l"(a), "l"(b));
}
__device__ __forceinline__ void unpk(unsigned long long v, float& lo, float& hi) {
    asm("mov.b64 {%0, %1}, %2;" : "=f"(lo), "=f"(hi) : "l"(v));
}

// ============================================================
// Kernel A1a: qk per output channel. 8 blocks x 128.
// ============================================================
__global__ void kA1a(const float* __restrict__ rims, const float* __restrict__ Wq,
                     const float* __restrict__ bq) {
    int o = blockIdx.x * 128 + threadIdx.x;
    int r = o >> 6;
    const float4* rrow = (const float4*)(rims + r * 64);
    const float4* wrow = (const float4*)(Wq + o * 64);
    float s = bq[o];
#pragma unroll
    for (int c4 = 0; c4 < 16; ++c4) {
        float4 w = wrow[c4];
        float4 rv = rrow[c4];
        s = fmaf(rv.x, w.x, s);
        s = fmaf(rv.y, w.y, s);
        s = fmaf(rv.z, w.z, s);
        s = fmaf(rv.w, w.w, s);
    }
    g_qkA[o] = fmaxf(s, 0.f);
}

// ============================================================
// Kernel A1b: null constants + compaction scan. 1 x 1024.
// ============================================================
__global__ void kA1b(const float* __restrict__ bk) {
    __shared__ float qs[1024];
    __shared__ int sc[1024];
    int o = threadIdx.x;
    float qk = g_qkA[o];
    float bko = bk[o];
    qs[o] = qk * fmaxf(bko, 0.f);
    int active = (qk > 0.f) ? 1 : 0;
    sc[o] = active;
    __syncthreads();
    if (o < 64) {
        float cn = 0.f;
#pragma unroll
        for (int d = 0; d < 16; ++d) cn += qs[o * 16 + d];
        g_cn[o] = cn;
    }
    for (int off = 1; off < 1024; off <<= 1) {
        int v = 0;
        if (o >= off) v = sc[o - off];
        __syncthreads();
        sc[o] += v;
        __syncthreads();
    }
    if (active) {
        int p = sc[o] - 1;
        g_src[p] = o;
        g_grp[p] = o >> 4;
        g_bkq[p] = bko * qk;
        g_scl[p] = qk;
    }
    int nact = sc[1023];
    int npad = (nact + 127) & ~127;
    if (o == 0) { g_npad = npad; g_nreal = nact; }
    if (o < npad - nact) {
        int p = nact + o;
        g_src[p] = 0;
        g_grp[p] = 64;
        g_bkq[p] = 0.f;
        g_scl[p] = 0.f;
    }
}

// ============================================================
// Kernel A2: transposed scaled compacted Wk -> g_Wkc[c][slot]. 32 x 256.
// ============================================================
__global__ void kA2(const float* __restrict__ Wk) {
    int gid = blockIdx.x * 256 + threadIdx.x;   // 8192
    int row = gid >> 3, seg = gid & 7;          // 8 channels per seg
    if (row >= g_npad) return;
    float scl = g_scl[row];
    int src = g_src[row];
    const float4* wr = (const float4*)(Wk + src * 64 + seg * 8);
    float4 w0 = __ldg(wr);
    float4 w1 = __ldg(wr + 1);
    int c = seg * 8;
    g_Wkc[(c + 0) * 1024 + row] = w0.x * scl;
    g_Wkc[(c + 1) * 1024 + row] = w0.y * scl;
    g_Wkc[(c + 2) * 1024 + row] = w0.z * scl;
    g_Wkc[(c + 3) * 1024 + row] = w0.w * scl;
    g_Wkc[(c + 4) * 1024 + row] = w1.x * scl;
    g_Wkc[(c + 5) * 1024 + row] = w1.y * scl;
    g_Wkc[(c + 6) * 1024 + row] = w1.z * scl;
    g_Wkc[(c + 7) * 1024 + row] = w1.w * scl;
}

// ============================================================
// Kernel W: one-time weight transposes. 33 blocks x 256.
// Wv/Wm: [rim][o][c] -> [rim][c][colperm(o)], colperm(o) = (o&15)*4 + (o>>4).
// ============================================================
__global__ void kW(const float* __restrict__ Wv, const float* __restrict__ Wm,
                   const float* __restrict__ Wo) {
    int mat = blockIdx.x;
    const float* src;
    float* dst;
    bool perm = true;
    if (mat < 16)      { src = Wv + mat * 4096;       dst = g_WvT + mat * 4096; }
    else if (mat < 32) { src = Wm + (mat - 16) * 4096; dst = g_WmT + (mat - 16) * 4096; }
    else               { src = Wo;                     dst = g_WoT; perm = false; }
    for (int e = threadIdx.x; e < 1024; e += 256) {
        int o = e >> 4, c4 = e & 15;
        float4 v = __ldg((const float4*)src + e);
        int col = perm ? ((o & 15) * 4 + (o >> 4)) : o;
        int c = c4 * 4;
        dst[(c + 0) * 64 + col] = v.x;
        dst[(c + 1) * 64 + col] = v.y;
        dst[(c + 2) * 64 + col] = v.z;
        dst[(c + 3) * 64 + col] = v.w;
    }
}

// ============================================================
// Kernel B: compacted keyf GEMM + scores + top-4. (unchanged)
// ============================================================
#define KB_WS   4096
#define KB_IP   (4096 + 64 * 132)
#define SMEM_B  ((4096 + 64 * 132 + 65 * 68) * 4)

__global__ void __launch_bounds__(256, 2) kB(const float* __restrict__ x) {
    extern __shared__ float sm[];
    float* xs = sm;
    float* ws = sm + KB_WS;
    float* ip = sm + KB_IP;

    const int tid  = threadIdx.x;
    const int pi0  = blockIdx.x * 64;
    const int bimg = pi0 >> 12;
    const int hw   = pi0 & 4095;
    const float* xbase = x + bimg * 262144 + hw;

    for (int e4 = tid; e4 < 1024; e4 += 256) {
        int c = e4 >> 4, p = (e4 & 15) << 2;
        *(float4*)(xs + c * 64 + p) = *(const float4*)(xbase + c * 4096 + p);
    }
    for (int e = tid; e < 65 * 68; e += 256) ip[e] = 0.f;

    const int tx = tid & 15;
    const int ty = tid >> 4;
    const int npad = g_npad;

    for (int o0 = 0; o0 < npad; o0 += 128) {
        __syncthreads();
        for (int e4 = tid; e4 < 2048; e4 += 256) {
            int c = e4 >> 5, o4 = (e4 & 31) << 2;
            *(float4*)(ws + c * 132 + o4) = *(const float4*)(g_Wkc + c * 1024 + o0 + o4);
        }
        __syncthreads();

        unsigned long long acc[16];
#pragma unroll
        for (int i = 0; i < 16; ++i) acc[i] = 0ull;
        const float* wbase = ws + ty * 8;
        const float* xrow  = xs + tx * 4;

#pragma unroll 8
        for (int k = 0; k < 64; ++k) {
            float4 xv = *(const float4*)(xrow + k * 64);
            unsigned long long xd0 = pk2(xv.x, xv.x);
            unsigned long long xd1 = pk2(xv.y, xv.y);
            unsigned long long xd2 = pk2(xv.z, xv.z);
            unsigned long long xd3 = pk2(xv.w, xv.w);
            ulonglong2 wa = *(const ulonglong2*)(wbase + k * 132);
            ulonglong2 wb = *(const ulonglong2*)(wbase + k * 132 + 4);
            fma2(acc[0],  wa.x, xd0); fma2(acc[1],  wa.x, xd1);
            fma2(acc[2],  wa.x, xd2); fma2(acc[3],  wa.x, xd3);
            fma2(acc[4],  wa.y, xd0); fma2(acc[5],  wa.y, xd1);
            fma2(acc[6],  wa.y, xd2); fma2(acc[7],  wa.y, xd3);
            fma2(acc[8],  wb.x, xd0); fma2(acc[9],  wb.x, xd1);
            fma2(acc[10], wb.x, xd2); fma2(acc[11], wb.x, xd3);
            fma2(acc[12], wb.y, xd0); fma2(acc[13], wb.y, xd1);
            fma2(acc[14], wb.y, xd2); fma2(acc[15], wb.y, xd3);
        }

        const int ob = o0 + ty * 8;
        int   grp[8];
        float bkq[8];
#pragma unroll
        for (int j = 0; j < 8; ++j) {
            grp[j] = __ldg(g_grp + ob + j);
            bkq[j] = __ldg(g_bkq + ob + j);
        }
#pragma unroll
        for (int px = 0; px < 4; ++px) {
            float s = 0.f;
            int gp = grp[0];
#pragma unroll
            for (int op = 0; op < 4; ++op) {
                float lo, hi;
                unpk(acc[op * 4 + px], lo, hi);
                int j0 = 2 * op;
                if (grp[j0] != gp) { atomicAdd(ip + gp * 68 + tx * 4 + px, s); s = 0.f; gp = grp[j0]; }
                s += fmaxf(lo + bkq[j0], 0.f);
                if (grp[j0 + 1] != gp) { atomicAdd(ip + gp * 68 + tx * 4 + px, s); s = 0.f; gp = grp[j0 + 1]; }
                s += fmaxf(hi + bkq[j0 + 1], 0.f);
            }
            atomicAdd(ip + gp * 68 + tx * 4 + px, s);
        }
    }
    __syncthreads();

    if (tid < 64) {
        int p = tid;
        float sc[16];
#pragma unroll
        for (int r = 0; r < 16; ++r) {
            float s = 0.f;
#pragma unroll
            for (int hd = 0; hd < 4; ++hd) {
                float v = ip[(r * 4 + hd) * 68 + p] - g_cn[r * 4 + hd];
                s += 1.f / (1.f + expf(-v));
            }
            sc[r] = s;
        }
        unsigned sel = 0;
#pragma unroll
        for (int kk = 0; kk < 4; ++kk) {
            int best = 0;
            float bvv = sc[0];
#pragma unroll
            for (int r = 1; r < 16; ++r)
                if (sc[r] > bvv) { bvv = sc[r]; best = r; }
            sel |= (unsigned)best << (8 * kk);
            sc[best] = -1e30f;
        }
        g_sel[pi0 + p] = sel;
    }
}

// ============================================================
// Kernel C: block = 256 px, 512 threads, grid 128.
// Same as round 10 plus tail-guarded GEMM tiles (s0 < wn).
// ============================================================
#define C_MACC 0
#define C_XG   17024
#define C_VB   25984
#define C_WS   34944
#define C_BIAS 52864
#define C_CNT  53120
#define C_RL   53152
#define SMEM_C ((53152 + 2048) * 4)

__global__ void __launch_bounds__(512, 1) kC(const float* __restrict__ x,
                                             const float* __restrict__ bv,
                                             const float* __restrict__ bm,
                                             const float* __restrict__ bo,
                                             float* __restrict__ out) {
    extern __shared__ float sm[];
    float* macc = sm + C_MACC;
    float* xg   = sm + C_XG;
    float* vb   = sm + C_VB;
    float* ws   = sm + C_WS;
    float* bvS  = sm + C_BIAS;        // [2][64]
    float* bmS  = bvS + 128;          // [2][64]
    int* rimcnt = (int*)(sm + C_CNT);
    int* pn     = rimcnt + 16;
    unsigned short* rimlist = (unsigned short*)(sm + C_RL);   // [16][256]

    const int tid  = threadIdx.x;
    const int pi0  = blockIdx.x * 256;
    const int bimg = pi0 >> 12;
    const int hwb  = pi0 & 4095;
    const float* xbase = x + bimg * 262144 + hwb;

    for (int e = tid; e < 17024; e += 512) macc[e] = 0.f;
    if (tid < 16) rimcnt[tid] = 0;
    __syncthreads();

    if (tid < 256) {
        unsigned sel = g_sel[pi0 + tid];
#pragma unroll
        for (int j = 0; j < 4; ++j) {
            int r = (sel >> (8 * j)) & 15;
            int slot = atomicAdd(&rimcnt[r], 1);
            rimlist[r * 256 + slot] = (unsigned short)tid;
        }
    }
    __syncthreads();
    if (tid < 16) pn[tid] = (rimcnt[tid] + 3) & ~3;
    __syncthreads();

    const int sq = tid >> 4, oq = tid & 15, s0 = sq * 4;

    for (int b = 0; b < 8; ++b) {
        const int r0 = 2 * b;
        const int pn0 = pn[r0];
        const int nsl = pn0 + pn[r0 + 1];

        // stage Wv/Wm (both rims) + biases
        for (int e = tid; e < 4096; e += 512) {
            int mat = e >> 11;
            int rest = e & 2047;
            int m = rest >> 10, c = (rest >> 4) & 63, o4 = rest & 15;
            const float* srcb = (mat ? g_WmT : g_WvT) + (r0 + m) * 4096 + c * 64 + o4 * 4;
            *(float4*)(ws + c * 280 + mat * 140 + m * 68 + o4 * 4) = *(const float4*)srcb;
        }
        if (tid < 128) {
            int m = tid >> 6, o = tid & 63;
            bvS[tid] = __ldg(bv + (r0 + m) * 64 + o);
            bmS[tid] = __ldg(bm + (r0 + m) * 64 + o);
        }
        __syncthreads();

        for (int w0 = 0; w0 < nsl; w0 += 128) {
            int wn = nsl - w0;
            if (wn > 128) wn = 128;
            // ---- gather: thread owns slot sl across 16 channels ----
            {
                int sl = tid & 127;
                int gs = w0 + sl;
                int mm = (gs >= pn0) ? 1 : 0;
                int rim = r0 + mm;
                int i = gs - (mm ? pn0 : 0);
                bool ok = (i < rimcnt[rim]);
                int pxl = ok ? (int)rimlist[rim * 256 + i] : 0;
                for (int c = tid >> 7; c < 64; c += 4) {
                    float v = ok ? __ldg(xbase + c * 4096 + pxl) : 0.f;
                    xg[c * 140 + sl] = v;
                }
            }
            __syncthreads();

            const int m2 = ((w0 + s0) >= pn0) ? 1 : 0;
            const bool live = (s0 < wn);

            // ---- val GEMM: 1 tile per thread (4 slots x out-quad oq) ----
            if (live) {
                const float* wcol = ws + m2 * 68 + oq * 4;
                unsigned long long acc[8];
#pragma unroll
                for (int i = 0; i < 8; ++i) acc[i] = 0ull;
#pragma unroll 4
                for (int c = 0; c < 64; ++c) {
                    float4 xv = *(const float4*)(xg + c * 140 + s0);
                    ulonglong2 wp = *(const ulonglong2*)(wcol + c * 280);
                    unsigned long long x0 = pk2(xv.x, xv.x);
                    unsigned long long x1 = pk2(xv.y, xv.y);
                    unsigned long long x2 = pk2(xv.z, xv.z);
                    unsigned long long x3 = pk2(xv.w, xv.w);
                    fma2(acc[0], wp.x, x0); fma2(acc[1], wp.x, x1);
                    fma2(acc[2], wp.x, x2); fma2(acc[3], wp.x, x3);
                    fma2(acc[4], wp.y, x0); fma2(acc[5], wp.y, x1);
                    fma2(acc[6], wp.y, x2); fma2(acc[7], wp.y, x3);
                }
                float b0 = bvS[m2 * 64 + oq];
                float b1 = bvS[m2 * 64 + oq + 16];
                float b2 = bvS[m2 * 64 + oq + 32];
                float b3 = bvS[m2 * 64 + oq + 48];
#pragma unroll
                for (int j = 0; j < 4; ++j) {
                    float lo, hi;
                    unpk(acc[j], lo, hi);
                    vb[(oq)      * 140 + s0 + j] = fmaxf(lo + b0, 0.f);
                    vb[(oq + 16) * 140 + s0 + j] = fmaxf(hi + b1, 0.f);
                    unpk(acc[4 + j], lo, hi);
                    vb[(oq + 32) * 140 + s0 + j] = fmaxf(lo + b2, 0.f);
                    vb[(oq + 48) * 140 + s0 + j] = fmaxf(hi + b3, 0.f);
                }
            }
            __syncthreads();

            // ---- merge GEMM + scatter ----
            if (live) {
                const float* wcol = ws + 140 + m2 * 68 + oq * 4;
                unsigned long long acc[8];
#pragma unroll
                for (int i = 0; i < 8; ++i) acc[i] = 0ull;
#pragma unroll 4
                for (int d = 0; d < 64; ++d) {
                    float4 xv = *(const float4*)(vb + d * 140 + s0);
                    ulonglong2 wp = *(const ulonglong2*)(wcol + d * 280);
                    unsigned long long x0 = pk2(xv.x, xv.x);
                    unsigned long long x1 = pk2(xv.y, xv.y);
                    unsigned long long x2 = pk2(xv.z, xv.z);
                    unsigned long long x3 = pk2(xv.w, xv.w);
                    fma2(acc[0], wp.x, x0); fma2(acc[1], wp.x, x1);
                    fma2(acc[2], wp.x, x2); fma2(acc[3], wp.x, x3);
                    fma2(acc[4], wp.y, x0); fma2(acc[5], wp.y, x1);
                    fma2(acc[6], wp.y, x2); fma2(acc[7], wp.y, x3);
                }
                float b0 = bmS[m2 * 64 + oq];
                float b1 = bmS[m2 * 64 + oq + 16];
                float b2 = bmS[m2 * 64 + oq + 32];
                float b3 = bmS[m2 * 64 + oq + 48];
                const int rim = r0 + m2;
                const int base = (w0 + s0) - (m2 ? pn0 : 0);
#pragma unroll
                for (int j = 0; j < 4; ++j) {
                    int i = base + j;
                    if (i < rimcnt[rim]) {
                        int pxl = (int)rimlist[rim * 256 + i];
                        float lo, hi;
                        unpk(acc[j], lo, hi);
                        atomicAdd(macc + (oq)      * 266 + pxl, lo + b0);
                        atomicAdd(macc + (oq + 16) * 266 + pxl, hi + b1);
                        unpk(acc[4 + j], lo, hi);
                        atomicAdd(macc + (oq + 32) * 266 + pxl, lo + b2);
                        atomicAdd(macc + (oq + 48) * 266 + pxl, hi + b3);
                    }
                }
            }
            __syncthreads();
        }
    }

    // mean+relu; stage Wo into ws cols 0..63 and bo into bvS
    for (int e = tid; e < 16384; e += 512) {
        int c = e >> 8, p = e & 255;
        macc[c * 266 + p] = fmaxf(macc[c * 266 + p] * 0.25f, 0.f);
    }
    for (int e4 = tid; e4 < 1024; e4 += 512) {
        int c = e4 >> 4, o4 = (e4 & 15) << 2;
        *(float4*)(ws + c * 280 + o4) = *(const float4*)(g_WoT + c * 64 + o4);
    }
    if (tid < 64) bvS[tid] = __ldg(bo + tid);
    __syncthreads();

    // projection: 1024 tiles = 128 pixel-pairs x 8 out-octets, 2 per thread
    for (int t = tid; t < 1024; t += 512) {
        int pq = t & 127, oc = t >> 7;
        unsigned long long acc[8];
#pragma unroll
        for (int j = 0; j < 8; ++j) acc[j] = 0ull;
#pragma unroll 4
        for (int c = 0; c < 64; ++c) {
            unsigned long long mv = *(const unsigned long long*)(macc + c * 266 + pq * 2);
            float4 wA = *(const float4*)(ws + c * 280 + oc * 8);
            float4 wB = *(const float4*)(ws + c * 280 + oc * 8 + 4);
            fma2(acc[0], mv, pk2(wA.x, wA.x));
            fma2(acc[1], mv, pk2(wA.y, wA.y));
            fma2(acc[2], mv, pk2(wA.z, wA.z));
            fma2(acc[3], mv, pk2(wA.w, wA.w));
            fma2(acc[4], mv, pk2(wB.x, wB.x));
            fma2(acc[5], mv, pk2(wB.y, wB.y));
            fma2(acc[6], mv, pk2(wB.z, wB.z));
            fma2(acc[7], mv, pk2(wB.w, wB.w));
        }
        float* outb = out + bimg * 262144 + hwb + pq * 2;
#pragma unroll
        for (int j = 0; j < 8; ++j) {
            int co = oc * 8 + j;
            float bov = bvS[co];
            float lo, hi;
            unpk(acc[j], lo, hi);
            float2 o2 = make_float2(fmaxf(lo + bov, 0.f), fmaxf(hi + bov, 0.f));
            *(float2*)(outb + co * 4096) = o2;
        }
    }
}

// ============================================================
extern "C" void kernel_launch(void* const* d_in, const int* in_sizes, int n_in,
                              void* d_out, int out_size) {
    const float* x    = (const float*)d_in[0];
    const float* rims = (const float*)d_in[1];
    const float* Wk   = (const float*)d_in[2];
    const float* bk   = (const float*)d_in[3];
    const float* Wv   = (const float*)d_in[4];
    const float* bv   = (const float*)d_in[5];
    const float* Wq   = (const float*)d_in[6];
    const float* bq   = (const float*)d_in[7];
    const float* Wm   = (const float*)d_in[8];
    const float* bm   = (const float*)d_in[9];
    const float* Wo   = (const float*)d_in[10];
    const float* bo   = (const float*)d_in[11];
    float* out = (float*)d_out;

    cudaFuncSetAttribute(kB, cudaFuncAttributeMaxDynamicSharedMemorySize, SMEM_B);
    cudaFuncSetAttribute(kC, cudaFuncAttributeMaxDynamicSharedMemorySize, SMEM_C);

    // Launch order chosen so the ncu capture (empirically launch index 3 mod n)
    // lands on kB this round.
    kA1a<<<8, 128>>>(rims, Wq, bq);          // 0
    kA1b<<<1, 1024>>>(bk);                   // 1
    kA2<<<32, 256>>>(Wk);                    // 2
    kB<<<512, 256, SMEM_B>>>(x);             // 3  <- profiled
    kW<<<33, 256>>>(Wv, Wm, Wo);             // 4
    kC<<<128, 512, SMEM_C>>>(x, bv, bm, bo, out);  // 5
}